// round 9
// baseline (speedup 1.0000x reference)
#include <cuda_runtime.h>
#include <cuda_bf16.h>
#include <math_constants.h>

// Problem constants (fixed shapes)
#define B_   8
#define C_   21
#define H_   512
#define W_   512
#define HW_  (H_ * W_)           // 262144 = 2^18
#define HW_SHIFT 18
#define NPIX (B_ * HW_)          // 2097152
#define MAX_M 0.5f
#define S_    30.0f

#define HIST_BLOCKS 512                 // 512 blk * 256 thr * 4 int4 = 2M labels
#define LOSS_ITERS  4
#define LOSS_STRIDE (NPIX / LOSS_ITERS) // 524288 threads
#define LOSS_BLOCKS (LOSS_STRIDE / 256) // 2048 blocks (~1.7 waves)

// Scratch (device globals — no allocations allowed)
__device__ int          g_parts[HIST_BLOCKS][C_];
__device__ float        g_mlist[C_];
__device__ double       g_loss;
__device__ unsigned int g_done;

// ---------------------------------------------------------------------------
// Kernel 1: per-block label histograms. 4 int4 loads batched up-front (MLP=4)
// so the dependent smem atomics overlap the DRAM latency. Block 0 zeroes the
// loss accumulator state (consumed only by strictly-later kernels).
// ---------------------------------------------------------------------------
__global__ __launch_bounds__(256) void hist_kernel(const int* __restrict__ target) {
    __shared__ int sh[8][C_];
    int wid = threadIdx.x >> 5;
    for (int i = threadIdx.x; i < 8 * C_; i += 256)
        (&sh[0][0])[i] = 0;
    if (blockIdx.x == 0 && threadIdx.x == 0) { g_loss = 0.0; g_done = 0u; }
    __syncthreads();

    const int4* t4 = reinterpret_cast<const int4*>(target);
    int4 a[4];
#pragma unroll
    for (int k = 0; k < 4; k++)
        a[k] = t4[blockIdx.x * 1024 + k * 256 + threadIdx.x];

#pragma unroll
    for (int k = 0; k < 4; k++) {
        atomicAdd(&sh[wid][a[k].x], 1);
        atomicAdd(&sh[wid][a[k].y], 1);
        atomicAdd(&sh[wid][a[k].z], 1);
        atomicAdd(&sh[wid][a[k].w], 1);
    }
    __syncthreads();

    if (threadIdx.x < C_) {
        int s = 0;
#pragma unroll
        for (int w = 0; w < 8; w++) s += sh[w][threadIdx.x];
        g_parts[blockIdx.x][threadIdx.x] = s;
    }
}

// ---------------------------------------------------------------------------
// Kernel 2: reduce partials -> counts -> m_list  (21 warps; warp w owns class w)
// ---------------------------------------------------------------------------
__global__ void mlist_kernel() {
    __shared__ float cnt[C_];
    int w    = threadIdx.x >> 5;   // 0..20
    int lane = threadIdx.x & 31;

    int s = 0;
    for (int p = lane; p < HIST_BLOCKS; p += 32) s += g_parts[p][w];
#pragma unroll
    for (int o = 16; o > 0; o >>= 1) s += __shfl_xor_sync(0xffffffffu, s, o);
    if (lane == 0) cnt[w] = (float)s;
    __syncthreads();

    if (w == 0) {
        float mi = 0.0f, m = -CUDART_INF_F;
        if (lane < C_) {
            mi = rsqrtf(sqrtf(cnt[lane] + 1e-4f));
            m  = mi;
        }
#pragma unroll
        for (int o = 16; o > 0; o >>= 1)
            m = fmaxf(m, __shfl_xor_sync(0xffffffffu, m, o));
        if (lane < C_) g_mlist[lane] = mi * (MAX_M / m);
    }
}

// ---------------------------------------------------------------------------
// Kernel 3: LDAM NLL. 4 sequential pixels per thread (grid 2048 -> ~1.7 waves,
// amortized block epilogue). Per pixel: single pass over 21 channels keeping
// v[] in registers; x_l captured by an in-loop register SELECT (no global
// re-gather, no per-channel margin math). Margin applied as an epilogue
// correction against the RAW max stabilizer:
//   exp args <= 0; target term >= exp(-S*MAX_M) = exp(-15) -> no over/underflow
//   s' = max(s - e_l, 0) + e_{l-m}   (fmax guards cancellation)
// Finalize fused via fenced done-counter.
// ---------------------------------------------------------------------------
__global__ __launch_bounds__(256) void loss_kernel(const float* __restrict__ pred,
                                                   const int*   __restrict__ target,
                                                   float*       __restrict__ out) {
    int t = blockIdx.x * 256 + threadIdx.x;

    float acc = 0.0f;
#pragma unroll 1
    for (int k = 0; k < LOSS_ITERS; k++) {
        int n  = k * LOSS_STRIDE + t;
        int b  = n >> HW_SHIFT;
        int hw = n & (HW_ - 1);
        const float* base = pred + (size_t)(b * C_) * HW_ + hw;

        int l = target[n];

        float v[C_];
        float maxv = -CUDART_INF_F;
        float xl   = 0.0f;
#pragma unroll
        for (int c = 0; c < C_; c++) {
            float x = __ldg(base + (size_t)c * HW_);
            v[c] = x;
            maxv = fmaxf(maxv, x);
            if (c == l) xl = x;           // register select, static index
        }

        float s = 0.0f;
#pragma unroll
        for (int c = 0; c < C_; c++)
            s += __expf(S_ * (v[c] - maxv));

        float m   = g_mlist[l];
        float el  = __expf(S_ * (xl - maxv));
        float elm = __expf(S_ * (xl - m - maxv));
        float sp  = fmaxf(s - el, 0.0f) + elm;
        acc += __logf(sp) + S_ * (maxv - (xl - m));
    }

    // Warp reduce, cross-warp via smem, one f64 atomic per block.
#pragma unroll
    for (int o = 16; o > 0; o >>= 1)
        acc += __shfl_xor_sync(0xffffffffu, acc, o);

    __shared__ float warp_sums[8];
    int lane = threadIdx.x & 31;
    int wid  = threadIdx.x >> 5;
    if (lane == 0) warp_sums[wid] = acc;
    __syncthreads();

    if (wid == 0) {
        float x = (lane < 8) ? warp_sums[lane] : 0.0f;
#pragma unroll
        for (int o = 4; o > 0; o >>= 1)
            x += __shfl_xor_sync(0xffffffffu, x, o);
        if (lane == 0) {
            atomicAdd(&g_loss, (double)x);
            __threadfence();
            unsigned int done = atomicAdd(&g_done, 1u);
            if (done == (unsigned int)(gridDim.x - 1)) {
                double total = atomicAdd(&g_loss, 0.0);
                out[0] = (float)(total * (1.0 / (double)NPIX));
            }
        }
    }
}

// ---------------------------------------------------------------------------
extern "C" void kernel_launch(void* const* d_in, const int* in_sizes, int n_in,
                              void* d_out, int out_size) {
    const float* pred   = (const float*)d_in[0];
    const int*   target = (const int*)d_in[1];
    float*       out    = (float*)d_out;

    hist_kernel<<<HIST_BLOCKS, 256>>>(target);
    mlist_kernel<<<1, C_ * 32>>>();
    loss_kernel<<<LOSS_BLOCKS, 256>>>(pred, target, out);
}